// round 6
// baseline (speedup 1.0000x reference)
#include <cuda_runtime.h>
#include <cuda_bf16.h>
#include <cstdint>

#define KK 4096
#define NPIX (64*32*256)

__device__ float g_zrest[NPIX];
__device__ float g_zflat[16384*32];
__device__ float g_zsq[16384];
__device__ float g_wsq[KK];
__device__ float g_pd[65536];
__device__ int   g_pi[65536];
__device__ int   g_tok[16384];
__device__ __nv_bfloat16 g_zbf[16384*128];
__device__ __nv_bfloat16 g_ebf[4096*128];
__device__ int g_cnt[16384*16];
__device__ int g_cand[16384*16*8];

typedef unsigned long long ull;

// ---------- fused init ----------
__global__ void k_init(const float* __restrict__ z, const float* __restrict__ w) {
    int bid = blockIdx.x, tid = threadIdx.x;
    if (bid < 2048) {
        int i = bid * 256 + tid;
        g_zrest[i] = z[i];
    } else if (bid < 2064) {
        int r = (bid - 2048) * 256 + tid;      // code 0..4095
        const float* p = w + r * 32;
        float s = 0.f;
#pragma unroll
        for (int c = 0; c < 32; c++) s = __fadd_rn(s, __fmul_rn(p[c], p[c]));
        g_wsq[r] = s;
        __nv_bfloat16* eb = g_ebf + (size_t)r * 128;
#pragma unroll
        for (int c = 0; c < 32; c++) {
            float v = p[c];
            __nv_bfloat16 hi = __float2bfloat16(v);
            __nv_bfloat16 lo = __float2bfloat16(v - __bfloat162float(hi));
            eb[c] = hi; eb[32 + c] = hi; eb[64 + c] = lo;
        }
        float h = -0.5f * s;
        __nv_bfloat16 hh = __float2bfloat16(h);
        __nv_bfloat16 hl = __float2bfloat16(h - __bfloat162float(hh));
        eb[96] = hh; eb[97] = hl;
        for (int i2 = 98; i2 < 128; i2++) eb[i2] = __float2bfloat16(0.f);
    } else if (bid < 2072) {
        // level-0 prep
        int warp = tid >> 5, lane = tid & 31;
        int t = (bid - 2064) * 8 + warp;
        const float* base = z + (t * 32 + lane) * 256;
        float s = 0.f;
        for (int dy = 0; dy < 16; dy++)
            for (int dx = 0; dx < 16; dx++)
                s = __fadd_rn(s, base[dy * 16 + dx]);
        float zd = __fmul_rn(s, 1.f / 256.f);
        g_zflat[t * 32 + lane] = zd;
        float q = __fmul_rn(zd, zd);
#pragma unroll
        for (int off = 16; off; off >>= 1)
            q = __fadd_rn(q, __shfl_xor_sync(0xffffffffu, q, off));
        if (lane == 0) g_zsq[t] = q;
    } else {
        // z-side constant columns: 96,97 = 1.0, pad 0
        int r = (bid - 2072) * 256 + tid;      // 0..16383
        __nv_bfloat16* zb = g_zbf + (size_t)r * 128;
        __nv_bfloat16 one = __float2bfloat16(1.f);
        zb[96] = one; zb[97] = one;
        for (int i2 = 98; i2 < 128; i2++) zb[i2] = __float2bfloat16(0.f);
    }
}

// ---------- scalar dist (levels 0-2 only) ----------
__global__ void __launch_bounds__(256) k_dist(const float* __restrict__ emb,
                                              int codesPerSplit, int iters,
                                              int tokClamp) {
    __shared__ float zs[32][128];
    __shared__ ull   es[32][64];
    __shared__ float ws[64];
    int tid = threadIdx.x;
    int tx = tid & 15, ty = tid >> 4;
    int tb = blockIdx.x * 128;

    for (int s = tid; s < 512; s += 256) {
        int tok = s >> 2, part = s & 3;
        int gt = tb + tok; if (gt > tokClamp) gt = tokClamp;
        const float4* p = (const float4*)(g_zflat + gt * 32 + part * 8);
        float4 a = p[0], b4 = p[1];
        int c0 = part * 8;
        zs[c0+0][tok]=a.x;  zs[c0+1][tok]=a.y;  zs[c0+2][tok]=a.z;  zs[c0+3][tok]=a.w;
        zs[c0+4][tok]=b4.x; zs[c0+5][tok]=b4.y; zs[c0+6][tok]=b4.z; zs[c0+7][tok]=b4.w;
    }
    float zq[8];
#pragma unroll
    for (int j = 0; j < 8; j++) {
        int gt = tb + ty * 8 + j; if (gt > tokClamp) gt = tokClamp;
        zq[j] = g_zsq[gt];
    }
    float bd[8]; int bk[8];
#pragma unroll
    for (int j = 0; j < 8; j++) { bd[j] = __int_as_float(0x7f800000); bk[j] = 0; }

    int kbase = blockIdx.y * codesPerSplit;
    for (int it = 0; it < iters; it++) {
        int kb = kbase + it * 64;
        __syncthreads();
        {
            int code = tid >> 2, part = tid & 3;
            const float4* p = (const float4*)(emb + (kb + code) * 32 + part * 8);
            float4 a = p[0], b4 = p[1];
            int c0 = part * 8;
            ull d0,d1,d2,d3,d4,d5,d6,d7;
            asm("mov.b64 %0, {%1, %1};" : "=l"(d0) : "f"(a.x));
            asm("mov.b64 %0, {%1, %1};" : "=l"(d1) : "f"(a.y));
            asm("mov.b64 %0, {%1, %1};" : "=l"(d2) : "f"(a.z));
            asm("mov.b64 %0, {%1, %1};" : "=l"(d3) : "f"(a.w));
            asm("mov.b64 %0, {%1, %1};" : "=l"(d4) : "f"(b4.x));
            asm("mov.b64 %0, {%1, %1};" : "=l"(d5) : "f"(b4.y));
            asm("mov.b64 %0, {%1, %1};" : "=l"(d6) : "f"(b4.z));
            asm("mov.b64 %0, {%1, %1};" : "=l"(d7) : "f"(b4.w));
            es[c0+0][code]=d0; es[c0+1][code]=d1; es[c0+2][code]=d2; es[c0+3][code]=d3;
            es[c0+4][code]=d4; es[c0+5][code]=d5; es[c0+6][code]=d6; es[c0+7][code]=d7;
        }
        if (tid < 64) ws[tid] = g_wsq[kb + tid];
        __syncthreads();

        ull acc[4][4];
#pragma unroll
        for (int p = 0; p < 4; p++)
#pragma unroll
            for (int k = 0; k < 4; k++) acc[p][k] = 0ull;
#pragma unroll 8
        for (int c = 0; c < 32; c++) {
            ulonglong2 za = *(const ulonglong2*)&zs[c][ty * 8];
            ulonglong2 zb = *(const ulonglong2*)&zs[c][ty * 8 + 4];
            ull zp[4] = {za.x, za.y, zb.x, zb.y};
            ulonglong2 e01 = *(const ulonglong2*)&es[c][tx * 4];
            ulonglong2 e23 = *(const ulonglong2*)&es[c][tx * 4 + 2];
            ull ed[4] = {e01.x, e01.y, e23.x, e23.y};
#pragma unroll
            for (int p = 0; p < 4; p++)
#pragma unroll
                for (int k = 0; k < 4; k++)
                    asm("fma.rn.f32x2 %0, %1, %2, %0;"
                        : "+l"(acc[p][k]) : "l"(zp[p]), "l"(ed[k]));
        }
#pragma unroll
        for (int p = 0; p < 4; p++) {
#pragma unroll
            for (int k = 0; k < 4; k++) {
                float lo, hi;
                asm("mov.b64 {%0, %1}, %2;" : "=f"(lo), "=f"(hi) : "l"(acc[p][k]));
                int kk = kb + tx * 4 + k;
                float wv = ws[tx * 4 + k];
                float d0 = __fadd_rn(__fadd_rn(zq[2*p],   wv), __fmul_rn(-2.f, lo));
                float d1 = __fadd_rn(__fadd_rn(zq[2*p+1], wv), __fmul_rn(-2.f, hi));
                if (d0 < bd[2*p])   { bd[2*p]   = d0; bk[2*p]   = kk; }
                if (d1 < bd[2*p+1]) { bd[2*p+1] = d1; bk[2*p+1] = kk; }
            }
        }
    }
#pragma unroll
    for (int j = 0; j < 8; j++) {
        float d = bd[j]; int k = bk[j];
#pragma unroll
        for (int off = 8; off; off >>= 1) {
            float od = __shfl_xor_sync(0xffffffffu, d, off, 16);
            int   ok = __shfl_xor_sync(0xffffffffu, k, off, 16);
            if (od < d || (od == d && ok < k)) { d = od; k = ok; }
        }
        if (tx == 0) {
            int t = tb + ty * 8 + j;
            if (t <= tokClamp) {
                g_pd[t * gridDim.y + blockIdx.y] = d;
                g_pi[t * gridDim.y + blockIdx.y] = k;
            }
        }
    }
}

// ---------- mma.sync bf16 GEMM + margin candidates (levels 3,4) ----------
#define DELTA_D 1e-3f
#define SROW 272               // 136 bf16 per row (conflict-free frag loads)
#define B_OFF (128 * SROW)     // 34816
#define SM_TOTAL (2 * 128 * SROW)  // 69632

__global__ void __launch_bounds__(256) k_gemm(int dummy) {
    extern __shared__ char dsm[];
    char* At = dsm;
    char* Bt = dsm + B_OFF;
    int tid = threadIdx.x;
    int wid = tid >> 5, lane = tid & 31;
    int g = lane >> 2, q = lane & 3;
    int tb = blockIdx.x * 128;
    int split = blockIdx.y;

    // stage A once: row = tid>>1, half = tid&1 (64 bf16 = 8 uint4)
    {
        int r = tid >> 1, h = tid & 1;
        const uint4* src = (const uint4*)(g_zbf + (size_t)(tb + r) * 128 + h * 64);
        uint4* dst = (uint4*)(At + r * SROW + h * 128);
#pragma unroll
        for (int j = 0; j < 8; j++) dst[j] = src[j];
    }

    int t0 = tb + wid * 16 + g;
    int t1 = t0 + 8;
    int cb0 = ((t0 * 4 + split) * 4 + q) * 8;
    int cb1 = ((t1 * 4 + split) * 4 + q) * 8;
    float best0 = -__int_as_float(0x7f800000), best1 = best0;
    int cnt0 = 0, cnt1 = 0;

    const char* Arow0 = At + (wid * 16 + g) * SROW + q * 4;
    const char* Brow0 = Bt + g * SROW + q * 4;

    for (int it = 0; it < 8; it++) {
        int code0 = split * 1024 + it * 128;
        __syncthreads();
        {
            int r = tid >> 1, h = tid & 1;
            const uint4* src = (const uint4*)(g_ebf + (size_t)(code0 + r) * 128 + h * 64);
            uint4* dst = (uint4*)(Bt + r * SROW + h * 128);
#pragma unroll
            for (int j = 0; j < 8; j++) dst[j] = src[j];
        }
        __syncthreads();

        float acc[16][4];
#pragma unroll
        for (int nt = 0; nt < 16; nt++)
#pragma unroll
            for (int c = 0; c < 4; c++) acc[nt][c] = 0.f;

#pragma unroll
        for (int k = 0; k < 8; k++) {
            uint32_t a0 = *(const uint32_t*)(Arow0 + k * 32);
            uint32_t a1 = *(const uint32_t*)(Arow0 + 8 * SROW + k * 32);
            uint32_t a2 = *(const uint32_t*)(Arow0 + k * 32 + 16);
            uint32_t a3 = *(const uint32_t*)(Arow0 + 8 * SROW + k * 32 + 16);
#pragma unroll
            for (int nt = 0; nt < 16; nt++) {
                uint32_t b0 = *(const uint32_t*)(Brow0 + nt * 8 * SROW + k * 32);
                uint32_t b1 = *(const uint32_t*)(Brow0 + nt * 8 * SROW + k * 32 + 16);
                asm volatile(
                    "mma.sync.aligned.m16n8k16.row.col.f32.bf16.bf16.f32 "
                    "{%0,%1,%2,%3}, {%4,%5,%6,%7}, {%8,%9}, {%0,%1,%2,%3};"
                    : "+f"(acc[nt][0]), "+f"(acc[nt][1]),
                      "+f"(acc[nt][2]), "+f"(acc[nt][3])
                    : "r"(a0), "r"(a1), "r"(a2), "r"(a3), "r"(b0), "r"(b1));
            }
        }

        // candidate scan: token t0 gets acc[nt][0..1], t1 gets acc[nt][2..3]
#pragma unroll
        for (int nt = 0; nt < 16; nt++) {
#pragma unroll
            for (int c = 0; c < 2; c++) {
                int k = code0 + nt * 8 + q * 2 + c;
                float D0 = acc[nt][c];
                if (D0 >= best0 - DELTA_D) {
                    if (D0 > best0 + DELTA_D) { best0 = D0; cnt0 = 0; }
                    else if (D0 > best0) best0 = D0;
                    if (cnt0 < 8) g_cand[cb0 + cnt0] = k;
                    cnt0++;
                }
                float D1 = acc[nt][c + 2];
                if (D1 >= best1 - DELTA_D) {
                    if (D1 > best1 + DELTA_D) { best1 = D1; cnt1 = 0; }
                    else if (D1 > best1) best1 = D1;
                    if (cnt1 < 8) g_cand[cb1 + cnt1] = k;
                    cnt1++;
                }
            }
        }
    }
    g_cnt[(t0 * 4 + split) * 4 + q] = cnt0;
    g_cnt[(t1 * 4 + split) * 4 + q] = cnt1;
}

// ---------- exact fp32 rerank (one warp per token) ----------
__device__ __forceinline__ float exact_d(const float* __restrict__ zr, float zq,
                                         const float* __restrict__ emb, int k) {
    const float* e = emb + k * 32;
    float acc = 0.f;
#pragma unroll
    for (int c = 0; c < 32; c++) acc = __fmaf_rn(zr[c], e[c], acc);
    float s1 = __fadd_rn(zq, g_wsq[k]);
    return __fadd_rn(s1, __fmul_rn(-2.f, acc));
}

__global__ void __launch_bounds__(256) k_rerank(const float* __restrict__ emb) {
    int t = (blockIdx.x * 256 + threadIdx.x) >> 5;
    int lane = threadIdx.x & 31;
    int cnts[16]; bool fb = false; int tot = 0;
#pragma unroll
    for (int s = 0; s < 16; s++) {
        int c = g_cnt[t * 16 + s];
        if (c > 8) { fb = true; c = 8; }
        cnts[s] = c; tot += c;
    }
    float zq = g_zsq[t];
    const float* zr = g_zflat + t * 32;
    float bd = __int_as_float(0x7f800000);
    int bk = 0x7fffffff;
    if (!fb) {
        for (int i = lane; i < tot; i += 32) {
            int idx = i, s = 0;
            while (idx >= cnts[s]) { idx -= cnts[s]; s++; }
            int k = g_cand[(t * 16 + s) * 8 + idx];
            float d = exact_d(zr, zq, emb, k);
            if (d < bd || (d == bd && k < bk)) { bd = d; bk = k; }
        }
    } else {
        for (int k = lane; k < 4096; k += 32) {
            float d = exact_d(zr, zq, emb, k);
            if (d < bd || (d == bd && k < bk)) { bd = d; bk = k; }
        }
    }
#pragma unroll
    for (int off = 16; off; off >>= 1) {
        float od = __shfl_xor_sync(0xffffffffu, bd, off);
        int   ok = __shfl_xor_sync(0xffffffffu, bk, off);
        if (od < bd || (od == bd && ok < bk)) { bd = od; bk = ok; }
    }
    if (lane == 0) g_tok[t] = bk;
}

// ---------- cubic weights ----------
template<int PN>
__device__ __forceinline__ void cubw(int o, float* w) {
    if (PN == 1) { w[0] = 1.f; return; }
    float s = __fadd_rn(__fmul_rn(__fadd_rn((float)o, 0.5f), (float)PN / 16.f), -0.5f);
    float tot = 0.f;
#pragma unroll
    for (int i = 0; i < PN; i++) {
        float x = fabsf(s - (float)i);
        float v;
        if (x >= 2.f)      v = 0.f;
        else if (x >= 1.f) v = ((-0.5f * x + 2.5f) * x - 4.f) * x + 2.f;
        else               v = ((1.5f * x - 2.5f) * x) * x + 1.f;
        w[i] = v; tot += v;
    }
#pragma unroll
    for (int i = 0; i < PN; i++) w[i] = w[i] / tot;
}

// ---------- fused up-sample + residual + next-level prep ----------
template<int PN, int PNN, bool WBF>
__global__ void __launch_bounds__(256) k_up(const float* __restrict__ emb,
                                            const float* __restrict__ outPrev,
                                            float* __restrict__ outCur,
                                            int isFirst, int KS, int useTok) {
    constexpr int NT = PN * PN;
    constexpr int SUB = 16 / PNN;
    __shared__ float pdp[512];
    __shared__ int   pip[512];
    __shared__ int   tok_s[NT];
    __shared__ float ew[NT][33];
    __shared__ float zt[32][256];
    int b = blockIdx.x;
    int tid = threadIdx.x;

    if (useTok) {
        if (tid < NT) tok_s[tid] = g_tok[b * NT + tid];
    } else {
        int tot = NT * KS;
        for (int i = tid; i < tot; i += 256) {
            pdp[i] = g_pd[b * tot + i];
            pip[i] = g_pi[b * tot + i];
        }
        __syncthreads();
        if (tid < NT) {
            float bdv = pdp[tid * KS]; int bkv = pip[tid * KS];
            for (int s = 1; s < KS; s++) {
                float d = pdp[tid * KS + s]; int k = pip[tid * KS + s];
                if (d < bdv || (d == bdv && k < bkv)) { bdv = d; bkv = k; }
            }
            tok_s[tid] = bkv;
        }
    }
    __syncthreads();

    for (int idx = tid; idx < NT * 8; idx += 256) {
        int token = idx >> 3, seg = idx & 7;
        float4 v = *(const float4*)(emb + tok_s[token] * 32 + seg * 4);
        ew[token][seg*4+0] = v.x; ew[token][seg*4+1] = v.y;
        ew[token][seg*4+2] = v.z; ew[token][seg*4+3] = v.w;
    }
    __syncthreads();

    int y = tid >> 4, x = tid & 15;
    float wy[PN], wx[PN];
    cubw<PN>(y, wy);
    cubw<PN>(x, wx);
#pragma unroll
    for (int c = 0; c < 32; c++) {
        float acc = 0.f;
#pragma unroll
        for (int j = 0; j < PN; j++) {
            float tmp = 0.f;
#pragma unroll
            for (int i = 0; i < PN; i++) tmp += wx[i] * ew[j * PN + i][c];
            acc += wy[j] * tmp;
        }
        int idx = (b * 32 + c) * 256 + y * 16 + x;
        float prev = isFirst ? 0.f : outPrev[idx];
        outCur[idx] = prev + acc;
        float nz = g_zrest[idx] - acc;
        g_zrest[idx] = nz;
        zt[c][tid] = nz;
    }
    __syncthreads();

    if (tid < PNN * PNN) {
        int ty2 = tid / PNN, tx2 = tid % PNN;
        float buf[32];
        float zqacc = 0.f;
#pragma unroll
        for (int c = 0; c < 32; c++) {
            float s = 0.f;
            for (int dy = 0; dy < SUB; dy++)
                for (int dx = 0; dx < SUB; dx++)
                    s = __fadd_rn(s, zt[c][(ty2 * SUB + dy) * 16 + tx2 * SUB + dx]);
            float zd = __fmul_rn(s, 1.f / (float)(SUB * SUB));
            buf[c] = zd;
            zqacc = __fadd_rn(zqacc, __fmul_rn(zd, zd));
        }
        int row = b * PNN * PNN + tid;
        float* dst = g_zflat + (size_t)row * 32;
#pragma unroll
        for (int s8 = 0; s8 < 8; s8++)
            *(float4*)(dst + s8 * 4) = make_float4(buf[s8*4], buf[s8*4+1],
                                                   buf[s8*4+2], buf[s8*4+3]);
        g_zsq[row] = zqacc;
        if (WBF) {
            __nv_bfloat16* zb = g_zbf + (size_t)row * 128;
#pragma unroll
            for (int c = 0; c < 32; c++) {
                float v = buf[c];
                __nv_bfloat16 hi = __float2bfloat16(v);
                __nv_bfloat16 lo = __float2bfloat16(v - __bfloat162float(hi));
                zb[c] = hi; zb[32 + c] = lo; zb[64 + c] = hi;
            }
        }
    }
}

// ---------- last level ----------
__global__ void __launch_bounds__(256) k_up_last(const float* __restrict__ emb,
                                                 const float* __restrict__ outPrev,
                                                 float* __restrict__ outCur) {
    __shared__ int tok_s[256];
    int b = blockIdx.x, tid = threadIdx.x;
    tok_s[tid] = g_tok[b * 256 + tid];
    __syncthreads();
    const float* e = emb + tok_s[tid] * 32;
#pragma unroll
    for (int c = 0; c < 32; c++) {
        int idx = (b * 32 + c) * 256 + tid;
        outCur[idx] = outPrev[idx] + e[c];
    }
}

extern "C" void kernel_launch(void* const* d_in, const int* in_sizes, int n_in,
                              void* d_out, int out_size) {
    const float* z = (const float*)d_in[0];
    const float* w = (const float*)d_in[1];
    float* out = (float*)d_out;

    static int inited = 0;
    cudaFuncSetAttribute(k_gemm, cudaFuncAttributeMaxDynamicSharedMemorySize, SM_TOTAL);
    (void)inited;

    k_init<<<2136, 256>>>(z, w);

    // levels 0-2: scalar path
    const int ntok012[3] = {64, 256, 1024};
    const int KSs[3]     = {64, 32, 16};
    for (int l = 0; l < 3; l++) {
        int KS = KSs[l];
        int cps = KK / KS;
        int iters = cps / 64;
        int gx = (ntok012[l] + 127) / 128;
        dim3 g(gx, KS);
        k_dist<<<g, 256>>>(w, cps, iters, ntok012[l] - 1);
        float* cur = out + (size_t)l * NPIX;
        const float* prev = (l == 0) ? out : out + (size_t)(l - 1) * NPIX;
        if      (l == 0) k_up<1, 2, false><<<64, 256>>>(w, prev, cur, 1, KS, 0);
        else if (l == 1) k_up<2, 4, false><<<64, 256>>>(w, prev, cur, 0, KS, 0);
        else             k_up<4, 8, true ><<<64, 256>>>(w, prev, cur, 0, KS, 0);
    }

    // level 3: tensor path (4096 tokens)
    k_gemm<<<dim3(32, 4), 256, SM_TOTAL>>>(0);
    k_rerank<<<512, 256>>>(w);
    k_up<8, 16, true><<<64, 256>>>(w, out + 2 * (size_t)NPIX, out + 3 * (size_t)NPIX,
                                   0, 0, 1);

    // level 4: tensor path (16384 tokens)
    k_gemm<<<dim3(128, 4), 256, SM_TOTAL>>>(0);
    k_rerank<<<2048, 256>>>(w);
    k_up_last<<<64, 256>>>(w, out + 3 * (size_t)NPIX, out + 4 * (size_t)NPIX);
}